// round 1
// baseline (speedup 1.0000x reference)
#include <cuda_runtime.h>
#include <math.h>

// Problem dims (fixed by reference setup_inputs)
#define NB     16
#define SS     512
#define HH     1024
#define VV     8000
#define LLAY   8
#define NHEADS 4
#define DHEAD  256
#define NTOK   (NB*SS)          // 8192

// ---------------- scratch (__device__ globals: no allocation allowed) ---------
__device__ float g_z [NTOK*HH];
__device__ float g_z1[NTOK*HH];
__device__ float g_q [NTOK*HH];
__device__ float g_k [NTOK*HH];
__device__ float g_v [NTOK*HH];
__device__ float g_o [NTOK*HH];          // attention out, [B,H,S,dh] contiguous
__device__ float g_f [NTOK*HH];
__device__ float g_g [NTOK*HH];
__device__ float g_p [NB*NHEADS*SS*SS];  // attention probs, 64 MB

// ---------------- reductions -------------------------------------------------
__device__ __forceinline__ float warp_sum(float v){
#pragma unroll
    for(int o=16;o;o>>=1) v += __shfl_xor_sync(0xffffffffu,v,o);
    return v;
}
__device__ __forceinline__ float warp_max(float v){
#pragma unroll
    for(int o=16;o;o>>=1) v = fmaxf(v,__shfl_xor_sync(0xffffffffu,v,o));
    return v;
}
template<int NW>
__device__ __forceinline__ float block_sum(float v, float* sh){
    v = warp_sum(v);
    if((threadIdx.x&31)==0) sh[threadIdx.x>>5]=v;
    __syncthreads();
    float t=0.f;
#pragma unroll
    for(int i=0;i<NW;i++) t+=sh[i];
    __syncthreads();
    return t;
}
template<int NW>
__device__ __forceinline__ float block_max(float v, float* sh){
    v = warp_max(v);
    if((threadIdx.x&31)==0) sh[threadIdx.x>>5]=v;
    __syncthreads();
    float t=-1e30f;
#pragma unroll
    for(int i=0;i<NW;i++) t=fmaxf(t,sh[i]);
    __syncthreads();
    return t;
}

// ---------------- GEMM: C = alpha*(A op(B)) + bias, optional exact-GELU ------
// NT: C[m,n] = sum_k A[m,k]*B[n,k]   (both row-major, contraction contiguous)
// NN: C[m,n] = sum_k A[m,k]*B[k,n]
// Batched via blockIdx.z with two-level offsets: off = (z/divz)*s1 + (z%divz)*s2
// Tile 128x64x8, 256 threads, 8x4 per thread. All shapes here divide exactly.
template<bool TRANSB, int EPI>
__global__ __launch_bounds__(256) void gemm_kernel(
    const float* __restrict__ A, const float* __restrict__ B,
    const float* __restrict__ bias, float* __restrict__ C,
    int M, int N, int K, int lda, int ldb, int ldc, float alpha,
    int divz, long long sA1, long long sA2, long long sB1, long long sB2,
    long long sC1, long long sC2)
{
    constexpr int BM=128, BN=64, BK=8;
    __shared__ float As[BK][BM];
    __shared__ float Bs[BK][BN];
    const int z = blockIdx.z;
    A += (long long)(z/divz)*sA1 + (long long)(z%divz)*sA2;
    B += (long long)(z/divz)*sB1 + (long long)(z%divz)*sB2;
    C += (long long)(z/divz)*sC1 + (long long)(z%divz)*sC2;
    const int m0 = blockIdx.y*BM, n0 = blockIdx.x*BN;
    const int tid = threadIdx.x;
    const int tm = tid >> 4, tn = tid & 15;

    float acc[8][4];
#pragma unroll
    for(int i=0;i<8;i++)
#pragma unroll
        for(int j=0;j<4;j++) acc[i][j]=0.f;

    for (int k0=0;k0<K;k0+=BK) {
#pragma unroll
        for (int r=0;r<4;r++){
            int e = tid + r*256;               // 128x8 A tile
            int m = e >> 3, kk = e & 7;
            As[kk][m] = A[(long long)(m0+m)*lda + (k0+kk)];
        }
#pragma unroll
        for (int r=0;r<2;r++){
            int e = tid + r*256;               // 64x8 B tile
            if (TRANSB) { int n = e>>3, kk=e&7; Bs[kk][n] = B[(long long)(n0+n)*ldb + (k0+kk)]; }
            else        { int kk = e>>6, n=e&63; Bs[kk][n] = B[(long long)(k0+kk)*ldb + (n0+n)]; }
        }
        __syncthreads();
#pragma unroll
        for (int kk=0;kk<BK;kk++){
            float a[8],b[4];
#pragma unroll
            for(int i=0;i<8;i++) a[i]=As[kk][tm*8+i];
#pragma unroll
            for(int j=0;j<4;j++) b[j]=Bs[kk][tn*4+j];
#pragma unroll
            for(int i=0;i<8;i++)
#pragma unroll
                for(int j=0;j<4;j++)
                    acc[i][j] = fmaf(a[i],b[j],acc[i][j]);
        }
        __syncthreads();
    }

#pragma unroll
    for(int i=0;i<8;i++){
        int m = m0 + tm*8 + i;
#pragma unroll
        for(int j=0;j<4;j++){
            int n = n0 + tn*4 + j;
            float c = acc[i][j]*alpha;
            if (bias) c += bias[n];
            if (EPI==1) c = 0.5f*c*(1.0f+erff(c*0.70710678118654752440f)); // exact gelu
            C[(long long)m*ldc + n] = c;
        }
    }
}

// ---------------- token embedding + sinusoidal PE ----------------------------
__global__ __launch_bounds__(256) void embed_kernel(
    const int* __restrict__ x, const float* __restrict__ emb, float* __restrict__ z)
{
    const int row = blockIdx.x;               // b*S+s
    const int s = row & (SS-1);
    const int tok = x[row];
    const int t = threadIdx.x;
#pragma unroll
    for(int i=0;i<4;i++){
        int c = t + (i<<8);
        int half = c >> 1;                    // div index uses exponent 2*half
        float dv = expf(-(float)(2*half) * (9.210340371976184f/(float)HH));
        float ang = (float)s * dv;
        float pe = (c & 1) ? cosf(ang) : sinf(ang);
        z[(long long)row*HH + c] = emb[(long long)tok*HH + c] + pe;
    }
}

// ---------------- fused residual-add + LayerNorm -----------------------------
__global__ __launch_bounds__(256) void add_ln_kernel(
    const float* __restrict__ X, const float* __restrict__ R,
    const float* __restrict__ g, const float* __restrict__ b, float* __restrict__ out)
{
    __shared__ float sh[8];
    const long long row = blockIdx.x;
    const float* x = X + row*HH;
    const float* r = R + row*HH;
    const int t = threadIdx.x;
    float v[4]; float s=0.f;
#pragma unroll
    for(int i=0;i<4;i++){ int c=t+(i<<8); v[i]=x[c]+r[c]; s+=v[i]; }
    float mean = block_sum<8>(s, sh) * (1.0f/(float)HH);
    float sq=0.f;
#pragma unroll
    for(int i=0;i<4;i++){ float d=v[i]-mean; sq+=d*d; }
    float var = block_sum<8>(sq, sh) * (1.0f/(float)HH);
    float rstd = rsqrtf(var + 1e-5f);
    float* o = out + row*HH;
#pragma unroll
    for(int i=0;i<4;i++){ int c=t+(i<<8); o[c]=(v[i]-mean)*rstd*g[c]+b[c]; }
}

// ---------------- causal masked softmax over S, + atten_last=1/denominator ---
__global__ __launch_bounds__(128) void attn_softmax_kernel(
    float* __restrict__ P, const int* __restrict__ lengths, float* __restrict__ attn_out)
{
    __shared__ float sh[4];
    const int idx = blockIdx.x;               // (b*NHEADS + h)*SS + q
    const int q = idx & (SS-1);
    const int b = idx >> 11;                  // /(NHEADS*SS)
    float* p = P + (long long)idx*SS;
    const int t = threadIdx.x;
    if (q >= lengths[b]) {                    // fully-masked query row -> zeros
#pragma unroll
        for(int i=0;i<4;i++) p[t+(i<<7)] = 0.f;
        if (attn_out && t==0) attn_out[idx] = 0.f;
        return;
    }
    float v[4]; float m=-1e30f;
#pragma unroll
    for(int i=0;i<4;i++){ int k=t+(i<<7); v[i]=(k<=q)?p[k]:-1e30f; m=fmaxf(m,v[i]); }
    m = block_max<4>(m, sh);
    float s=0.f;
#pragma unroll
    for(int i=0;i<4;i++){ v[i]=expf(v[i]-m); s+=v[i]; }      // masked -> exp(-1e30)=0
    s = block_sum<4>(s, sh);
    float r = 1.0f/s;
#pragma unroll
    for(int i=0;i<4;i++) p[t+(i<<7)] = v[i]*r;
    if (attn_out && t==0) attn_out[idx] = r;  // max prob of softmax row = 1/sum
}

// ---------------- in-place softmax over vocab (8000) -------------------------
__global__ __launch_bounds__(256) void vocab_softmax_kernel(float* __restrict__ logits)
{
    __shared__ float sh[8];
    const long long row = blockIdx.x;
    float* p = logits + row*VV;
    const int t = threadIdx.x;
    float v[32]; float m=-1e30f;
#pragma unroll
    for(int i=0;i<32;i++){ int k=t+(i<<8); v[i]=(k<VV)?p[k]:-1e30f; m=fmaxf(m,v[i]); }
    m = block_max<8>(m, sh);
    float s=0.f;
#pragma unroll
    for(int i=0;i<32;i++){ v[i]=expf(v[i]-m); s+=v[i]; }
    s = block_sum<8>(s, sh);
    float r = 1.0f/s;
#pragma unroll
    for(int i=0;i<32;i++){ int k=t+(i<<8); if(k<VV) p[k]=v[i]*r; }
}

// ---------------- host-side launch helpers -----------------------------------
static void launch_gemm(const float*A,const float*B,const float*bias,float*C,
    int M,int N,int K,int lda,int ldb,int ldc,float alpha,bool transb,bool gelu_ep,
    int batch,int divz,long long sA1,long long sA2,long long sB1,long long sB2,
    long long sC1,long long sC2)
{
    dim3 grid(N/64, M/128, batch);
    if (transb) {
        if (gelu_ep)
            gemm_kernel<true,1><<<grid,256>>>(A,B,bias,C,M,N,K,lda,ldb,ldc,alpha,divz,sA1,sA2,sB1,sB2,sC1,sC2);
        else
            gemm_kernel<true,0><<<grid,256>>>(A,B,bias,C,M,N,K,lda,ldb,ldc,alpha,divz,sA1,sA2,sB1,sB2,sC1,sC2);
    } else {
        gemm_kernel<false,0><<<grid,256>>>(A,B,bias,C,M,N,K,lda,ldb,ldc,alpha,divz,sA1,sA2,sB1,sB2,sC1,sC2);
    }
}

extern "C" void kernel_launch(void* const* d_in, const int* in_sizes, int n_in,
                              void* d_out, int out_size)
{
    const int*   x       = (const int*)  d_in[0];
    const int*   lengths = (const int*)  d_in[1];
    const float* emb     = (const float*)d_in[2];
    const float* Wq = (const float*)d_in[3];
    const float* bq = (const float*)d_in[4];
    const float* Wk = (const float*)d_in[5];
    const float* bk = (const float*)d_in[6];
    const float* Wv = (const float*)d_in[7];
    const float* bv = (const float*)d_in[8];
    const float* W1 = (const float*)d_in[9];
    const float* b1 = (const float*)d_in[10];
    const float* W2 = (const float*)d_in[11];
    const float* b2 = (const float*)d_in[12];
    const float* g1 = (const float*)d_in[13];
    const float* be1= (const float*)d_in[14];
    const float* g2 = (const float*)d_in[15];
    const float* be2= (const float*)d_in[16];
    const float* Wfc= (const float*)d_in[17];
    const float* bfc= (const float*)d_in[18];
    float* out      = (float*)d_out;
    float* attn_out = out + (long long)NB*SS*VV;   // [B,HEADS,S] after y_prim

    float *z,*z1,*q,*k,*v,*o,*f,*gg,*p;
    cudaGetSymbolAddress((void**)&z,  g_z);
    cudaGetSymbolAddress((void**)&z1, g_z1);
    cudaGetSymbolAddress((void**)&q,  g_q);
    cudaGetSymbolAddress((void**)&k,  g_k);
    cudaGetSymbolAddress((void**)&v,  g_v);
    cudaGetSymbolAddress((void**)&o,  g_o);
    cudaGetSymbolAddress((void**)&f,  g_f);
    cudaGetSymbolAddress((void**)&gg, g_g);
    cudaGetSymbolAddress((void**)&p,  g_p);

    const long long SH  = (long long)SS*HH;       // token stride per batch
    const long long SS2 = (long long)SS*SS;
    const long long SD  = (long long)SS*DHEAD;

    // embedding + positional encoding
    embed_kernel<<<NTOK,256>>>(x, emb, z);

    for (int l=0;l<LLAY;l++){
        const float* Wq_l = Wq + (long long)l*HH*HH;
        const float* Wk_l = Wk + (long long)l*HH*HH;
        const float* Wv_l = Wv + (long long)l*HH*HH;
        const float* W1_l = W1 + (long long)l*HH*HH;
        const float* W2_l = W2 + (long long)l*HH*HH;

        // Q,K,V projections: [8192,1024] = z @ W^T + b
        launch_gemm(z, Wq_l, bq+l*HH, q, NTOK,HH,HH, HH,HH,HH, 1.f,true,false, 1,1,0,0,0,0,0,0);
        launch_gemm(z, Wk_l, bk+l*HH, k, NTOK,HH,HH, HH,HH,HH, 1.f,true,false, 1,1,0,0,0,0,0,0);
        launch_gemm(z, Wv_l, bv+l*HH, v, NTOK,HH,HH, HH,HH,HH, 1.f,true,false, 1,1,0,0,0,0,0,0);

        // scores: P[b,h] = Q_bh @ K_bh^T / 32   (batch=64, z=b*4+h)
        launch_gemm(q, k, nullptr, p, SS,SS,DHEAD, HH,HH,SS, 1.0f/32.0f, true,false,
                    NB*NHEADS, NHEADS,
                    SH, DHEAD,            // A offset: b*S*H + h*dh
                    SH, DHEAD,            // B offset: same
                    (long long)NHEADS*SS2, SS2);  // C offset: z*S*S

        // masked softmax (+ atten_last from final layer)
        attn_softmax_kernel<<<NB*NHEADS*SS,128>>>(p, lengths, (l==LLAY-1)?attn_out:nullptr);

        // O[b,h] = P_bh @ V_bh  (NN), stored [B,H,S,dh] contiguous
        launch_gemm(p, v, nullptr, o, SS,DHEAD,SS, SS,HH,DHEAD, 1.f,false,false,
                    NB*NHEADS, NHEADS,
                    (long long)NHEADS*SS2, SS2,   // A offset: z*S*S
                    SH, DHEAD,                    // B offset: b*S*H + h*dh
                    (long long)NHEADS*SD, SD);    // C offset: z*S*dh

        // faithful reshape bug == identity on flat memory: read g_o linearly
        add_ln_kernel<<<NTOK,256>>>(z, o, g1+l*HH, be1+l*HH, z1);

        // FFN: gelu(z1 @ W1^T + b1) @ W2^T + b2
        launch_gemm(z1, W1_l, b1+l*HH, f,  NTOK,HH,HH, HH,HH,HH, 1.f,true,true,  1,1,0,0,0,0,0,0);
        launch_gemm(f,  W2_l, b2+l*HH, gg, NTOK,HH,HH, HH,HH,HH, 1.f,true,false, 1,1,0,0,0,0,0,0);

        add_ln_kernel<<<NTOK,256>>>(z1, gg, g2+l*HH, be2+l*HH, z);
    }

    // out_fc = z @ Wfc^T + bfc   (reuse g_q)
    launch_gemm(z, Wfc, bfc, q, NTOK,HH,HH, HH,HH,HH, 1.f,true,false, 1,1,0,0,0,0,0,0);
    // logits = out_fc @ emb^T, straight into d_out (N=8000 = 125 * 64 exact)
    launch_gemm(q, emb, nullptr, out, NTOK,VV,HH, HH,HH,VV, 1.f,true,false, 1,1,0,0,0,0,0,0);
    // softmax in place over vocab
    vocab_softmax_kernel<<<NTOK,256>>>(out);
}

// round 3
// speedup vs baseline: 1.9720x; 1.9720x over previous
#include <cuda_runtime.h>
#include <cuda_bf16.h>
#include <math.h>
#include <stdint.h>

// Problem dims (fixed by reference setup_inputs)
#define NB     16
#define SS     512
#define HH     1024
#define VV     8000
#define LLAY   8
#define NHEADS 4
#define DHEAD  256
#define NTOK   (NB*SS)          // 8192

// ---------------- scratch (__device__ globals: no allocation allowed) ---------
__device__ float g_z [NTOK*HH];
__device__ float g_z1[NTOK*HH];
__device__ float g_q [NTOK*HH];
__device__ float g_k [NTOK*HH];
__device__ float g_v [NTOK*HH];
__device__ float g_o [NTOK*HH];          // attention out, [B,H,S,dh] contiguous
__device__ float g_f [NTOK*HH];
__device__ float g_g [NTOK*HH];
__device__ float g_p [NB*NHEADS*SS*SS];  // attention probs, 64 MB

// ---------------- bf16 hi/lo split helpers -----------------------------------
__device__ __forceinline__ void split2(float x, float y, uint32_t& hi, uint32_t& lo){
    __nv_bfloat162 h = __floats2bfloat162_rn(x, y);
    float rx = x - __bfloat162float(h.x);
    float ry = y - __bfloat162float(h.y);
    __nv_bfloat162 l = __floats2bfloat162_rn(rx, ry);
    hi = *(uint32_t*)&h;
    lo = *(uint32_t*)&l;
}

__device__ __forceinline__ void mma_bf16(float* c, const uint32_t* a, const uint32_t* b){
    asm volatile("mma.sync.aligned.m16n8k16.row.col.f32.bf16.bf16.f32 "
        "{%0,%1,%2,%3}, {%4,%5,%6,%7}, {%8,%9}, {%0,%1,%2,%3};"
        : "+f"(c[0]),"+f"(c[1]),"+f"(c[2]),"+f"(c[3])
        : "r"(a[0]),"r"(a[1]),"r"(a[2]),"r"(a[3]), "r"(b[0]),"r"(b[1]));
}

// ================= bf16x3 tensor-core GEMM ====================================
// C = alpha*(A op(B)) + bias, optional exact GELU.
// BNT=true : NT, B row-major [N,K] (contraction contiguous)
// BNT=false: NN, B row-major [K,N]
// A row-major [M,K]. Tile 128x128x32, 256 threads, warps 2(m)x4(n).
// Batched via blockIdx.z: off = (z/divz)*s1 + (z%divz)*s2.
// M,K multiples of 128/32. N guarded only on the NT path (logits N=8000).
template<bool BNT, int EPI>
__global__ void __launch_bounds__(256) tgemm(
    const float* __restrict__ A, const float* __restrict__ B,
    const float* __restrict__ bias, float* __restrict__ C,
    int M, int N, int K, int lda, int ldb, int ldc, float alpha,
    int divz, long long sA1, long long sA2, long long sB1, long long sB2,
    long long sC1, long long sC2)
{
    __shared__ uint32_t Ahi[16][136], Alo[16][136], Bhi[16][136], Blo[16][136];

    const int z = blockIdx.z;
    A += (long long)(z/divz)*sA1 + (long long)(z%divz)*sA2;
    B += (long long)(z/divz)*sB1 + (long long)(z%divz)*sB2;
    C += (long long)(z/divz)*sC1 + (long long)(z%divz)*sC2;
    const int m0 = blockIdx.y*128, n0 = blockIdx.x*128;
    const int tid = threadIdx.x;
    const int wid = tid>>5, lane = tid&31;
    const int g = lane>>2, t = lane&3;
    const int m0w = (wid&1)*64, n0w = (wid>>1)*32;
    const int lrow = tid & 31;        // for LDG/STS mapping
    const int lc4  = tid >> 5;        // 0..7

    float acc[4][4][4];
#pragma unroll
    for (int i=0;i<4;i++)
#pragma unroll
        for (int j=0;j<4;j++)
#pragma unroll
            for (int r=0;r<4;r++) acc[i][j][r]=0.f;

    const int nch = K >> 5;
    float4 av[4], bv[4];

    // ---- prologue LDG chunk 0 ----
    {
        const int kc = 0;
#pragma unroll
        for (int i=0;i<4;i++)
            av[i] = *(const float4*)&A[(long long)(m0+lrow+32*i)*lda + kc + lc4*4];
        if (BNT){
#pragma unroll
            for (int i=0;i<4;i++){
                int n = n0 + lrow + 32*i;
                bv[i] = (n < N) ? *(const float4*)&B[(long long)n*ldb + kc + lc4*4]
                                : make_float4(0.f,0.f,0.f,0.f);
            }
        } else {
#pragma unroll
            for (int ti=0;ti<2;ti++){
                int idx = tid + 256*ti; int p = idx>>5, n4 = idx&31;
                bv[2*ti]   = *(const float4*)&B[(long long)(kc+2*p  )*ldb + n0 + n4*4];
                bv[2*ti+1] = *(const float4*)&B[(long long)(kc+2*p+1)*ldb + n0 + n4*4];
            }
        }
    }

    for (int c=0; c<nch; c++){
        // ---- STS: split to bf16 hi/lo, pack k-pairs ----
#pragma unroll
        for (int i=0;i<4;i++){
            int row = lrow + 32*i;
            uint32_t h0,l0,h1,l1;
            split2(av[i].x, av[i].y, h0, l0);
            split2(av[i].z, av[i].w, h1, l1);
            Ahi[2*lc4  ][row] = h0;  Alo[2*lc4  ][row] = l0;
            Ahi[2*lc4+1][row] = h1;  Alo[2*lc4+1][row] = l1;
        }
        if (BNT){
#pragma unroll
            for (int i=0;i<4;i++){
                int row = lrow + 32*i;
                uint32_t h0,l0,h1,l1;
                split2(bv[i].x, bv[i].y, h0, l0);
                split2(bv[i].z, bv[i].w, h1, l1);
                Bhi[2*lc4  ][row] = h0;  Blo[2*lc4  ][row] = l0;
                Bhi[2*lc4+1][row] = h1;  Blo[2*lc4+1][row] = l1;
            }
        } else {
#pragma unroll
            for (int ti=0;ti<2;ti++){
                int idx = tid + 256*ti; int p = idx>>5, n4 = idx&31;
                const float4 r0 = bv[2*ti], r1 = bv[2*ti+1];
                uint32_t ph[4], pl[4];
                split2(r0.x, r1.x, ph[0], pl[0]);
                split2(r0.y, r1.y, ph[1], pl[1]);
                split2(r0.z, r1.z, ph[2], pl[2]);
                split2(r0.w, r1.w, ph[3], pl[3]);
                *(uint4*)&Bhi[p][n4*4] = make_uint4(ph[0],ph[1],ph[2],ph[3]);
                *(uint4*)&Blo[p][n4*4] = make_uint4(pl[0],pl[1],pl[2],pl[3]);
            }
        }
        __syncthreads();

        // ---- prefetch next chunk into regs (overlaps MMA below) ----
        if (c+1 < nch){
            const int kc = (c+1)*32;
#pragma unroll
            for (int i=0;i<4;i++)
                av[i] = *(const float4*)&A[(long long)(m0+lrow+32*i)*lda + kc + lc4*4];
            if (BNT){
#pragma unroll
                for (int i=0;i<4;i++){
                    int n = n0 + lrow + 32*i;
                    bv[i] = (n < N) ? *(const float4*)&B[(long long)n*ldb + kc + lc4*4]
                                    : make_float4(0.f,0.f,0.f,0.f);
                }
            } else {
#pragma unroll
                for (int ti=0;ti<2;ti++){
                    int idx = tid + 256*ti; int p = idx>>5, n4 = idx&31;
                    bv[2*ti]   = *(const float4*)&B[(long long)(kc+2*p  )*ldb + n0 + n4*4];
                    bv[2*ti+1] = *(const float4*)&B[(long long)(kc+2*p+1)*ldb + n0 + n4*4];
                }
            }
        }

        // ---- compute: 2 k-steps of m16n8k16, 3 split terms ----
#pragma unroll
        for (int ks=0; ks<2; ks++){
            uint32_t ah[4][4], al[4][4];
            const int pr = ks*8 + t;
#pragma unroll
            for (int i=0;i<4;i++){
                int m = m0w + i*16 + g;
                ah[i][0] = Ahi[pr  ][m];   ah[i][1] = Ahi[pr  ][m+8];
                ah[i][2] = Ahi[pr+4][m];   ah[i][3] = Ahi[pr+4][m+8];
                al[i][0] = Alo[pr  ][m];   al[i][1] = Alo[pr  ][m+8];
                al[i][2] = Alo[pr+4][m];   al[i][3] = Alo[pr+4][m+8];
            }
#pragma unroll
            for (int j=0;j<4;j++){
                int n = n0w + j*8 + g;
                uint32_t bh[2] = { Bhi[pr][n], Bhi[pr+4][n] };
                uint32_t bl[2] = { Blo[pr][n], Blo[pr+4][n] };
#pragma unroll
                for (int i=0;i<4;i++){
                    mma_bf16(acc[i][j], ah[i], bh);
                    mma_bf16(acc[i][j], al[i], bh);
                    mma_bf16(acc[i][j], ah[i], bl);
                }
            }
        }
        __syncthreads();
    }

    // ---- epilogue ----
#pragma unroll
    for (int i=0;i<4;i++){
        const int r0 = m0 + m0w + i*16 + g;
        const int r1 = r0 + 8;
#pragma unroll
        for (int j=0;j<4;j++){
            const int col = n0 + n0w + j*8 + 2*t;
            if (col < N){
                float b0=0.f, b1=0.f;
                if (bias){ b0 = bias[col]; b1 = bias[col+1]; }
                float c0 = acc[i][j][0]*alpha + b0;
                float c1 = acc[i][j][1]*alpha + b1;
                float c2 = acc[i][j][2]*alpha + b0;
                float c3 = acc[i][j][3]*alpha + b1;
                if (EPI==1){
                    c0 = 0.5f*c0*(1.0f+erff(c0*0.70710678118654752440f));
                    c1 = 0.5f*c1*(1.0f+erff(c1*0.70710678118654752440f));
                    c2 = 0.5f*c2*(1.0f+erff(c2*0.70710678118654752440f));
                    c3 = 0.5f*c3*(1.0f+erff(c3*0.70710678118654752440f));
                }
                *(float2*)&C[(long long)r0*ldc + col] = make_float2(c0,c1);
                *(float2*)&C[(long long)r1*ldc + col] = make_float2(c2,c3);
            }
        }
    }
}

// ---------------- reductions -------------------------------------------------
__device__ __forceinline__ float warp_sum(float v){
#pragma unroll
    for(int o=16;o;o>>=1) v += __shfl_xor_sync(0xffffffffu,v,o);
    return v;
}
__device__ __forceinline__ float warp_max(float v){
#pragma unroll
    for(int o=16;o;o>>=1) v = fmaxf(v,__shfl_xor_sync(0xffffffffu,v,o));
    return v;
}
template<int NW>
__device__ __forceinline__ float block_sum(float v, float* sh){
    v = warp_sum(v);
    if((threadIdx.x&31)==0) sh[threadIdx.x>>5]=v;
    __syncthreads();
    float t=0.f;
#pragma unroll
    for(int i=0;i<NW;i++) t+=sh[i];
    __syncthreads();
    return t;
}
template<int NW>
__device__ __forceinline__ float block_max(float v, float* sh){
    v = warp_max(v);
    if((threadIdx.x&31)==0) sh[threadIdx.x>>5]=v;
    __syncthreads();
    float t=-1e30f;
#pragma unroll
    for(int i=0;i<NW;i++) t=fmaxf(t,sh[i]);
    __syncthreads();
    return t;
}

// ---------------- token embedding + sinusoidal PE ----------------------------
__global__ __launch_bounds__(256) void embed_kernel(
    const int* __restrict__ x, const float* __restrict__ emb, float* __restrict__ z)
{
    const int row = blockIdx.x;
    const int s = row & (SS-1);
    const int tok = x[row];
    const int t = threadIdx.x;
#pragma unroll
    for(int i=0;i<4;i++){
        int c = t + (i<<8);
        int half = c >> 1;
        float dv = expf(-(float)(2*half) * (9.210340371976184f/(float)HH));
        float ang = (float)s * dv;
        float pe = (c & 1) ? cosf(ang) : sinf(ang);
        z[(long long)row*HH + c] = emb[(long long)tok*HH + c] + pe;
    }
}

// ---------------- fused residual-add + LayerNorm -----------------------------
__global__ __launch_bounds__(256) void add_ln_kernel(
    const float* __restrict__ X, const float* __restrict__ R,
    const float* __restrict__ g, const float* __restrict__ b, float* __restrict__ out)
{
    __shared__ float sh[8];
    const long long row = blockIdx.x;
    const float* x = X + row*HH;
    const float* r = R + row*HH;
    const int t = threadIdx.x;
    float v[4]; float s=0.f;
#pragma unroll
    for(int i=0;i<4;i++){ int c=t+(i<<8); v[i]=x[c]+r[c]; s+=v[i]; }
    float mean = block_sum<8>(s, sh) * (1.0f/(float)HH);
    float sq=0.f;
#pragma unroll
    for(int i=0;i<4;i++){ float d=v[i]-mean; sq+=d*d; }
    float var = block_sum<8>(sq, sh) * (1.0f/(float)HH);
    float rstd = rsqrtf(var + 1e-5f);
    float* o = out + row*HH;
#pragma unroll
    for(int i=0;i<4;i++){ int c=t+(i<<8); o[c]=(v[i]-mean)*rstd*g[c]+b[c]; }
}

// ---------------- causal masked softmax over S, + atten_last=1/denominator ---
__global__ __launch_bounds__(128) void attn_softmax_kernel(
    float* __restrict__ P, const int* __restrict__ lengths, float* __restrict__ attn_out)
{
    __shared__ float sh[4];
    const int idx = blockIdx.x;
    const int q = idx & (SS-1);
    const int b = idx >> 11;
    float* p = P + (long long)idx*SS;
    const int t = threadIdx.x;
    if (q >= lengths[b]) {
#pragma unroll
        for(int i=0;i<4;i++) p[t+(i<<7)] = 0.f;
        if (attn_out && t==0) attn_out[idx] = 0.f;
        return;
    }
    float v[4]; float m=-1e30f;
#pragma unroll
    for(int i=0;i<4;i++){ int k=t+(i<<7); v[i]=(k<=q)?p[k]:-1e30f; m=fmaxf(m,v[i]); }
    m = block_max<4>(m, sh);
    float s=0.f;
#pragma unroll
    for(int i=0;i<4;i++){ v[i]=expf(v[i]-m); s+=v[i]; }
    s = block_sum<4>(s, sh);
    float r = 1.0f/s;
#pragma unroll
    for(int i=0;i<4;i++) p[t+(i<<7)] = v[i]*r;
    if (attn_out && t==0) attn_out[idx] = r;
}

// ---------------- in-place softmax over vocab (8000) -------------------------
__global__ __launch_bounds__(256) void vocab_softmax_kernel(float* __restrict__ logits)
{
    __shared__ float sh[8];
    const long long row = blockIdx.x;
    float* p = logits + row*VV;
    const int t = threadIdx.x;
    float v[32]; float m=-1e30f;
#pragma unroll
    for(int i=0;i<32;i++){ int k=t+(i<<8); v[i]=(k<VV)?p[k]:-1e30f; m=fmaxf(m,v[i]); }
    m = block_max<8>(m, sh);
    float s=0.f;
#pragma unroll
    for(int i=0;i<32;i++){ v[i]=expf(v[i]-m); s+=v[i]; }
    s = block_sum<8>(s, sh);
    float r = 1.0f/s;
#pragma unroll
    for(int i=0;i<32;i++){ int k=t+(i<<8); if(k<VV) p[k]=v[i]*r; }
}

// ---------------- host-side launch helper ------------------------------------
static void launch_tgemm(const float*A,const float*B,const float*bias,float*C,
    int M,int N,int K,int lda,int ldb,int ldc,float alpha,bool bnt,bool gelu_ep,
    int batch,int divz,long long sA1,long long sA2,long long sB1,long long sB2,
    long long sC1,long long sC2)
{
    dim3 grid((N+127)/128, M/128, batch);
    if (bnt){
        if (gelu_ep)
            tgemm<true,1><<<grid,256>>>(A,B,bias,C,M,N,K,lda,ldb,ldc,alpha,divz,sA1,sA2,sB1,sB2,sC1,sC2);
        else
            tgemm<true,0><<<grid,256>>>(A,B,bias,C,M,N,K,lda,ldb,ldc,alpha,divz,sA1,sA2,sB1,sB2,sC1,sC2);
    } else {
        tgemm<false,0><<<grid,256>>>(A,B,bias,C,M,N,K,lda,ldb,ldc,alpha,divz,sA1,sA2,sB1,sB2,sC1,sC2);
    }
}

extern "C" void kernel_launch(void* const* d_in, const int* in_sizes, int n_in,
                              void* d_out, int out_size)
{
    const int*   x       = (const int*)  d_in[0];
    const int*   lengths = (const int*)  d_in[1];
    const float* emb     = (const float*)d_in[2];
    const float* Wq = (const float*)d_in[3];
    const float* bq = (const float*)d_in[4];
    const float* Wk = (const float*)d_in[5];
    const float* bk = (const float*)d_in[6];
    const float* Wv = (const float*)d_in[7];
    const float* bv = (const float*)d_in[8];
    const float* W1 = (const float*)d_in[9];
    const float* b1 = (const float*)d_in[10];
    const float* W2 = (const float*)d_in[11];
    const float* b2 = (const float*)d_in[12];
    const float* g1 = (const float*)d_in[13];
    const float* be1= (const float*)d_in[14];
    const float* g2 = (const float*)d_in[15];
    const float* be2= (const float*)d_in[16];
    const float* Wfc= (const float*)d_in[17];
    const float* bfc= (const float*)d_in[18];
    float* out      = (float*)d_out;
    float* attn_out = out + (long long)NB*SS*VV;

    float *z,*z1,*q,*k,*v,*o,*f,*gg,*p;
    cudaGetSymbolAddress((void**)&z,  g_z);
    cudaGetSymbolAddress((void**)&z1, g_z1);
    cudaGetSymbolAddress((void**)&q,  g_q);
    cudaGetSymbolAddress((void**)&k,  g_k);
    cudaGetSymbolAddress((void**)&v,  g_v);
    cudaGetSymbolAddress((void**)&o,  g_o);
    cudaGetSymbolAddress((void**)&f,  g_f);
    cudaGetSymbolAddress((void**)&gg, g_g);
    cudaGetSymbolAddress((void**)&p,  g_p);

    const long long SH  = (long long)SS*HH;
    const long long SS2 = (long long)SS*SS;
    const long long SD  = (long long)SS*DHEAD;

    embed_kernel<<<NTOK,256>>>(x, emb, z);

    for (int l=0;l<LLAY;l++){
        const float* Wq_l = Wq + (long long)l*HH*HH;
        const float* Wk_l = Wk + (long long)l*HH*HH;
        const float* Wv_l = Wv + (long long)l*HH*HH;
        const float* W1_l = W1 + (long long)l*HH*HH;
        const float* W2_l = W2 + (long long)l*HH*HH;

        // Q,K,V projections: [8192,1024] = z @ W^T + b   (NT)
        launch_tgemm(z, Wq_l, bq+l*HH, q, NTOK,HH,HH, HH,HH,HH, 1.f,true,false, 1,1,0,0,0,0,0,0);
        launch_tgemm(z, Wk_l, bk+l*HH, k, NTOK,HH,HH, HH,HH,HH, 1.f,true,false, 1,1,0,0,0,0,0,0);
        launch_tgemm(z, Wv_l, bv+l*HH, v, NTOK,HH,HH, HH,HH,HH, 1.f,true,false, 1,1,0,0,0,0,0,0);

        // scores: P[b,h] = Q_bh @ K_bh^T / 32   (NT, batch=64, z=b*4+h)
        launch_tgemm(q, k, nullptr, p, SS,SS,DHEAD, HH,HH,SS, 1.0f/32.0f, true,false,
                     NB*NHEADS, NHEADS,
                     SH, DHEAD, SH, DHEAD,
                     (long long)NHEADS*SS2, SS2);

        attn_softmax_kernel<<<NB*NHEADS*SS,128>>>(p, lengths, (l==LLAY-1)?attn_out:nullptr);

        // O[b,h] = P_bh @ V_bh   (NN), stored [B,H,S,dh] contiguous
        launch_tgemm(p, v, nullptr, o, SS,DHEAD,SS, SS,HH,DHEAD, 1.f,false,false,
                     NB*NHEADS, NHEADS,
                     (long long)NHEADS*SS2, SS2,
                     SH, DHEAD,
                     (long long)NHEADS*SD, SD);

        // faithful reshape bug == identity on flat memory: read g_o linearly
        add_ln_kernel<<<NTOK,256>>>(z, o, g1+l*HH, be1+l*HH, z1);

        // FFN: gelu(z1 @ W1^T + b1) @ W2^T + b2   (NT)
        launch_tgemm(z1, W1_l, b1+l*HH, f,  NTOK,HH,HH, HH,HH,HH, 1.f,true,true,  1,1,0,0,0,0,0,0);
        launch_tgemm(f,  W2_l, b2+l*HH, gg, NTOK,HH,HH, HH,HH,HH, 1.f,true,false, 1,1,0,0,0,0,0,0);

        add_ln_kernel<<<NTOK,256>>>(z1, gg, g2+l*HH, be2+l*HH, z);
    }

    // out_fc = z @ Wfc^T + bfc (reuse g_q)
    launch_tgemm(z, Wfc, bfc, q, NTOK,HH,HH, HH,HH,HH, 1.f,true,false, 1,1,0,0,0,0,0,0);
    // logits = out_fc @ emb^T, straight into d_out (N=8000 guarded tiles)
    launch_tgemm(q, emb, nullptr, out, NTOK,VV,HH, HH,HH,VV, 1.f,true,false, 1,1,0,0,0,0,0,0);
    vocab_softmax_kernel<<<NTOK,256>>>(out);
}